// round 15
// baseline (speedup 1.0000x reference)
#include <cuda_runtime.h>
#include <cuda_fp16.h>
#include <cstdint>

// Problem constants
#define BB      2
#define TT      2048
#define NH      12
#define DH      64
#define CC      768      // d_model
#define C3      2304     // 3*d_model
#define MM      (BB*TT)  // 4096 rows

// Scratch (device globals — no runtime allocation allowed)
__device__ __half g_qkvh[(size_t)MM * C3];    // [4096, 2304] fp16
__device__ __half g_atth[(size_t)MM * CC];    // [4096, 768]  fp16
__device__ __half g_xh[(size_t)MM * CC];      // x fp16
__device__ __half g_wqkvh[(size_t)C3 * CC];   // Wqkv^T fp16 [2304][768]
__device__ __half g_wouth[(size_t)CC * CC];   // Wout^T fp16 [768][768]

// ---------------------------------------------------------------------------
// helpers
// ---------------------------------------------------------------------------
__device__ __forceinline__ float ex2f(float x) {
    float r; asm("ex2.approx.f32 %0, %1;" : "=f"(r) : "f"(x)); return r;
}
__device__ __forceinline__ unsigned packh2(float lo, float hi) {
    __half2 h = __floats2half2_rn(lo, hi);
    return *reinterpret_cast<unsigned*>(&h);
}
__device__ __forceinline__ unsigned h2ex2(unsigned h) {
    unsigned r; asm("ex2.approx.f16x2 %0, %1;" : "=r"(r) : "r"(h)); return r;
}
__device__ __forceinline__ float2 h2f2(unsigned h) {
    __half2 v = *reinterpret_cast<__half2*>(&h);
    return __half22float2(v);
}
__device__ __forceinline__ void mma_f16(float c[4], const unsigned a[4], const unsigned b[2]) {
    asm volatile(
        "mma.sync.aligned.m16n8k16.row.col.f32.f16.f16.f32 "
        "{%0,%1,%2,%3},{%4,%5,%6,%7},{%8,%9},{%0,%1,%2,%3};"
        : "+f"(c[0]), "+f"(c[1]), "+f"(c[2]), "+f"(c[3])
        : "r"(a[0]), "r"(a[1]), "r"(a[2]), "r"(a[3]), "r"(b[0]), "r"(b[1]));
}
__device__ __forceinline__ void cp16s(unsigned dst_saddr, const void* src) {
    asm volatile("cp.async.cg.shared.global [%0], [%1], 16;" :: "r"(dst_saddr), "l"(src));
}
__device__ __forceinline__ void cp_commit() {
    asm volatile("cp.async.commit_group;");
}
template<int N> __device__ __forceinline__ void cp_wait() {
    asm volatile("cp.async.wait_group %0;" :: "n"(N));
}
__device__ __forceinline__ unsigned saddr(const void* p) {
    return (unsigned)__cvta_generic_to_shared(p);
}
// ldmatrix x4 (b16), transposed — V fragments
__device__ __forceinline__ void ldsm4t(unsigned r[4], unsigned addr) {
    asm volatile("ldmatrix.sync.aligned.m8n8.x4.trans.shared.b16 {%0,%1,%2,%3}, [%4];"
                 : "=r"(r[0]), "=r"(r[1]), "=r"(r[2]), "=r"(r[3]) : "r"(addr));
}

// ---------------------------------------------------------------------------
// Fused pre-pass: x f32->f16, both weight transposes, AND zero d_out
// (needed by the split-K atomic output projection).
// ---------------------------------------------------------------------------
#define NBX   ((MM * CC / 4) / 256)          // 3072
#define NBWQ  ((C3 / 32) * (CC / 32))        // 1728
#define NBWO  ((CC / 32) * (CC / 32))        // 576
#define NBZ   ((MM * CC / 4) / 256)          // 3072  (zero out, float4)
#define NB_PRE (NBX + NBWQ + NBWO + NBZ)

__global__ __launch_bounds__(256)
void prepass_kernel(const float* __restrict__ x,
                    const float* __restrict__ Wqkv,
                    const float* __restrict__ Wout,
                    __half* __restrict__ xh,
                    __half* __restrict__ wqkvh,
                    __half* __restrict__ wouth,
                    float* __restrict__ outz)
{
    __shared__ float t[32][33];
    const int bid = blockIdx.x;
    const int tid = threadIdx.x;

    if (bid < NBX) {
        int i = bid * 256 + tid;
        float4 v = ((const float4*)x)[i];
        ((__half2*)xh)[2 * i]     = __floats2half2_rn(v.x, v.y);
        ((__half2*)xh)[2 * i + 1] = __floats2half2_rn(v.z, v.w);
        return;
    }
    if (bid >= NBX + NBWQ + NBWO) {
        int i = (bid - NBX - NBWQ - NBWO) * 256 + tid;
        ((float4*)outz)[i] = make_float4(0.f, 0.f, 0.f, 0.f);
        return;
    }
    const float* in; __half* outp; int K, N, bx, by;
    if (bid < NBX + NBWQ) {
        int tI = bid - NBX;
        bx = tI % (C3 / 32); by = tI / (C3 / 32);
        in = Wqkv; outp = wqkvh; K = CC; N = C3;
    } else {
        int tI = bid - NBX - NBWQ;
        bx = tI % (CC / 32); by = tI / (CC / 32);
        in = Wout; outp = wouth; K = CC; N = CC;
    }
    int n0 = bx * 32, k0 = by * 32;
    int tx = tid & 31, ty = tid >> 5;    // 32 x 8
#pragma unroll
    for (int j = 0; j < 4; j++)
        t[ty + j * 8][tx] = in[(size_t)(k0 + ty + j * 8) * N + n0 + tx];
    __syncthreads();
#pragma unroll
    for (int j = 0; j < 4; j++)
        outp[(size_t)(n0 + ty + j * 8) * K + k0 + tx] = __float2half_rn(t[tx][ty + j * 8]);
}

// ---------------------------------------------------------------------------
// FP16 tensor-core GEMM with bias (128x128 tile; measured best for QKV):
// 4 warps (128 thr), warp tile 64x64, BK=64, 2-stage cp.async.
// ---------------------------------------------------------------------------
#define GSTAGE_B 36864
#define GEMM_SMEM (2 * GSTAGE_B)

template<bool HALF_OUT>
__global__ __launch_bounds__(128, 2)
void gemm_f16(const __half* __restrict__ A, const __half* __restrict__ Bt,
              const float* __restrict__ bias, void* __restrict__ Cv,
              int M, int N, int K, float qmul)
{
    extern __shared__ char smg[];
    const unsigned base = saddr(smg);

    const int tid  = threadIdx.x;
    const int lane = tid & 31;
    const int w    = tid >> 5;
    const int wm   = (w >> 1) * 64;
    const int wn   = (w & 1) * 64;
    const int g    = lane >> 2;
    const int tig  = lane & 3;
    const int rowBase = blockIdx.y * 128;
    const int colBase = blockIdx.x * 128;

    float acc[4][8][4];
#pragma unroll
    for (int mt = 0; mt < 4; mt++)
#pragma unroll
        for (int nt = 0; nt < 8; nt++)
#pragma unroll
            for (int j = 0; j < 4; j++) acc[mt][nt][j] = 0.f;

    auto loadTile = [&](int k0, int s) {
        unsigned ab = base + (unsigned)s * GSTAGE_B;
        unsigned bb = ab + 18432u;
#pragma unroll
        for (int i = 0; i < 8; i++) {
            int idx = tid + i * 128;
            int r = idx >> 3, c = idx & 7;
            cp16s(ab + r * 144 + c * 16, A  + (size_t)(rowBase + r) * K + k0 + c * 8);
        }
#pragma unroll
        for (int i = 0; i < 8; i++) {
            int idx = tid + i * 128;
            int r = idx >> 3, c = idx & 7;
            cp16s(bb + r * 144 + c * 16, Bt + (size_t)(colBase + r) * K + k0 + c * 8);
        }
    };

    loadTile(0, 0);
    cp_commit();

    int buf = 0;
    for (int k0 = 0; k0 < K; k0 += 64) {
        if (k0 + 64 < K) { loadTile(k0 + 64, buf ^ 1); cp_commit(); cp_wait<1>(); }
        else             { cp_wait<0>(); }
        __syncthreads();

        const unsigned* As = (const unsigned*)(smg + buf * GSTAGE_B);
        const unsigned* Bs = As + 18432 / 4;

#pragma unroll
        for (int ks = 0; ks < 4; ks++) {
            unsigned af[4][4], bf[8][2];
#pragma unroll
            for (int mt = 0; mt < 4; mt++) {
                int m = wm + mt * 16 + g;
                af[mt][0] = As[m * 36 + tig + 8 * ks];
                af[mt][1] = As[(m + 8) * 36 + tig + 8 * ks];
                af[mt][2] = As[m * 36 + tig + 4 + 8 * ks];
                af[mt][3] = As[(m + 8) * 36 + tig + 4 + 8 * ks];
            }
#pragma unroll
            for (int nt = 0; nt < 8; nt++) {
                int n = wn + nt * 8 + g;
                bf[nt][0] = Bs[n * 36 + tig + 8 * ks];
                bf[nt][1] = Bs[n * 36 + tig + 4 + 8 * ks];
            }
#pragma unroll
            for (int mt = 0; mt < 4; mt++)
#pragma unroll
                for (int nt = 0; nt < 8; nt++)
                    mma_f16(acc[mt][nt], af[mt], bf[nt]);
        }
        __syncthreads();
        buf ^= 1;
    }

#pragma unroll
    for (int mt = 0; mt < 4; mt++) {
        int r0 = rowBase + wm + mt * 16 + g;
#pragma unroll
        for (int nt = 0; nt < 8; nt++) {
            int c = colBase + wn + nt * 8 + 2 * tig;
            float2 b2 = *(const float2*)(bias + c);
            float sc = (c < CC) ? qmul : 1.f;
            float v00 = (acc[mt][nt][0] + b2.x) * sc, v01 = (acc[mt][nt][1] + b2.y) * sc;
            float v10 = (acc[mt][nt][2] + b2.x) * sc, v11 = (acc[mt][nt][3] + b2.y) * sc;
            if (HALF_OUT) {
                __half* C = (__half*)Cv;
                *(unsigned*)(C + (size_t)r0 * N + c)       = packh2(v00, v01);
                *(unsigned*)(C + (size_t)(r0 + 8) * N + c) = packh2(v10, v11);
            } else {
                float* C = (float*)Cv;
                *(float2*)(C + (size_t)r0 * N + c)       = make_float2(v00, v01);
                *(float2*)(C + (size_t)(r0 + 8) * N + c) = make_float2(v10, v11);
            }
        }
    }
}

// ---------------------------------------------------------------------------
// FP16 GEMM, 128x64 block tile, 4 warps (R12 config) + SPLIT-K=2:
// blockIdx.z selects K half; partial sums accumulated into fp32 C via
// atomicAdd (C pre-zeroed in the prepass). Split 0 adds bias.
// smem: 2 stages x (A[128][72] + B[64][72]) halves = 55296 B; 3 blocks/SM.
// ---------------------------------------------------------------------------
#define G64_STAGE_B 27648
#define G64_SMEM (2 * G64_STAGE_B)

__global__ __launch_bounds__(128, 3)
void gemm_f16_n64_sk(const __half* __restrict__ A, const __half* __restrict__ Bt,
                     const float* __restrict__ bias, float* __restrict__ C,
                     int M, int N, int K)
{
    extern __shared__ char smg[];
    const unsigned base = saddr(smg);

    const int tid  = threadIdx.x;
    const int lane = tid & 31;
    const int w    = tid >> 5;
    const int wm   = w * 32;
    const int g    = lane >> 2;
    const int tig  = lane & 3;
    const int rowBase = blockIdx.y * 128;
    const int colBase = blockIdx.x * 64;
    const int kHalf   = K >> 1;
    const int kStart  = blockIdx.z * kHalf;
    const bool addBias = (blockIdx.z == 0);

    float acc[2][8][4];
#pragma unroll
    for (int mt = 0; mt < 2; mt++)
#pragma unroll
        for (int nt = 0; nt < 8; nt++)
#pragma unroll
            for (int j = 0; j < 4; j++) acc[mt][nt][j] = 0.f;

    auto loadTile = [&](int k0, int s) {
        unsigned ab = base + (unsigned)s * G64_STAGE_B;
        unsigned bb = ab + 18432u;
#pragma unroll
        for (int i = 0; i < 8; i++) {
            int idx = tid + i * 128;
            int r = idx >> 3, c = idx & 7;
            cp16s(ab + r * 144 + c * 16, A  + (size_t)(rowBase + r) * K + k0 + c * 8);
        }
#pragma unroll
        for (int i = 0; i < 4; i++) {
            int idx = tid + i * 128;
            int r = idx >> 3, c = idx & 7;
            cp16s(bb + r * 144 + c * 16, Bt + (size_t)(colBase + r) * K + k0 + c * 8);
        }
    };

    loadTile(kStart, 0);
    cp_commit();

    int buf = 0;
    for (int k0 = kStart; k0 < kStart + kHalf; k0 += 64) {
        if (k0 + 64 < kStart + kHalf) { loadTile(k0 + 64, buf ^ 1); cp_commit(); cp_wait<1>(); }
        else                          { cp_wait<0>(); }
        __syncthreads();

        const unsigned* As = (const unsigned*)(smg + buf * G64_STAGE_B);
        const unsigned* Bs = As + 18432 / 4;

#pragma unroll
        for (int ks = 0; ks < 4; ks++) {
            unsigned af[2][4], bf[8][2];
#pragma unroll
            for (int mt = 0; mt < 2; mt++) {
                int m = wm + mt * 16 + g;
                af[mt][0] = As[m * 36 + tig + 8 * ks];
                af[mt][1] = As[(m + 8) * 36 + tig + 8 * ks];
                af[mt][2] = As[m * 36 + tig + 4 + 8 * ks];
                af[mt][3] = As[(m + 8) * 36 + tig + 4 + 8 * ks];
            }
#pragma unroll
            for (int nt = 0; nt < 8; nt++) {
                int n = nt * 8 + g;
                bf[nt][0] = Bs[n * 36 + tig + 8 * ks];
                bf[nt][1] = Bs[n * 36 + tig + 4 + 8 * ks];
            }
#pragma unroll
            for (int mt = 0; mt < 2; mt++)
#pragma unroll
                for (int nt = 0; nt < 8; nt++)
                    mma_f16(acc[mt][nt], af[mt], bf[nt]);
        }
        __syncthreads();
        buf ^= 1;
    }

#pragma unroll
    for (int mt = 0; mt < 2; mt++) {
        int r0 = rowBase + wm + mt * 16 + g;
#pragma unroll
        for (int nt = 0; nt < 8; nt++) {
            int c = colBase + nt * 8 + 2 * tig;
            float bx = 0.f, by = 0.f;
            if (addBias) { float2 b2 = *(const float2*)(bias + c); bx = b2.x; by = b2.y; }
            atomicAdd(C + (size_t)r0 * N + c,           acc[mt][nt][0] + bx);
            atomicAdd(C + (size_t)r0 * N + c + 1,       acc[mt][nt][1] + by);
            atomicAdd(C + (size_t)(r0 + 8) * N + c,     acc[mt][nt][2] + bx);
            atomicAdd(C + (size_t)(r0 + 8) * N + c + 1, acc[mt][nt][3] + by);
        }
    }
}

// ---------------------------------------------------------------------------
// Causal flash attention (R12 version, measured best):
// paired q-tiles, 4 warps x M=32, f16x2 softmax, 2-stage cp.async K/V,
// V via ldmatrix.trans.
// smem: Q[128][72] | 2 x (K[64][72] + V[64][72]) = 55296 B -> 2 blocks/SM.
// ---------------------------------------------------------------------------
#define FQ_B     18432
#define FKV_B    18432
#define FLASH_SMEM (FQ_B + 2 * FKV_B)

__global__ __launch_bounds__(128, 2)
void flash_f16(const __half* __restrict__ qkv, __half* __restrict__ out)
{
    extern __shared__ char smf[];
    const unsigned base = saddr(smf);

    const int b    = blockIdx.z;
    const int h    = blockIdx.y;
    const int tid  = threadIdx.x;
    const int lane = tid & 31;
    const int w    = tid >> 5;
    const int g    = lane >> 2;
    const int tig  = lane & 3;
    const int m0   = w * 32;
    const int nq   = gridDim.x * 2;
    const unsigned vlane = (unsigned)((lane & 15) * 144 + (lane >> 4) * 16);

    auto loadKV = [&](int kb, int s) {
        unsigned kbase = base + FQ_B + (unsigned)s * FKV_B;
        unsigned vbase = kbase + 9216u;
        const __half* kp = qkv + (size_t)(b * TT + kb * 64) * C3 + CC + h * DH;
#pragma unroll
        for (int i = 0; i < 4; i++) {
            int idx = tid + i * 128;
            int r = idx >> 3, c = idx & 7;
            const __half* rp = kp + (size_t)r * C3 + c * 8;
            cp16s(kbase + r * 144 + c * 16, rp);
            cp16s(vbase + r * 144 + c * 16, rp + CC);
        }
    };

    const int qts[2] = { nq - 1 - (int)blockIdx.x, (int)blockIdx.x };

    for (int qi = 0; qi < 2; qi++) {
        const int qt = qts[qi];

        loadKV(0, 0);
        cp_commit();

        {
            const __half* qp = qkv + (size_t)(b * TT + qt * 128) * C3 + h * DH;
#pragma unroll
            for (int i = 0; i < 8; i++) {
                int idx = tid + i * 128;
                int r = idx >> 3, c = idx & 7;
                *(uint4*)(smf + r * 144 + c * 16) =
                    *(const uint4*)(qp + (size_t)r * C3 + c * 8);
            }
        }
        __syncthreads();

        unsigned qf[2][4][4];
        {
            const unsigned* Qs = (const unsigned*)smf;
#pragma unroll
            for (int mi = 0; mi < 2; mi++) {
                int m = m0 + mi * 16 + g;
#pragma unroll
                for (int kt = 0; kt < 4; kt++) {
                    qf[mi][kt][0] = Qs[m * 36 + tig + 8 * kt];
                    qf[mi][kt][1] = Qs[(m + 8) * 36 + tig + 8 * kt];
                    qf[mi][kt][2] = Qs[m * 36 + tig + 4 + 8 * kt];
                    qf[mi][kt][3] = Qs[(m + 8) * 36 + tig + 4 + 8 * kt];
                }
            }
        }

        float o[2][8][4];
#pragma unroll
        for (int mi = 0; mi < 2; mi++)
#pragma unroll
            for (int nt = 0; nt < 8; nt++)
#pragma unroll
                for (int j = 0; j < 4; j++) o[mi][nt][j] = 0.f;

        float mr[2][2] = {{-1e30f, -1e30f}, {-1e30f, -1e30f}};
        float l[2][2]  = {{0.f, 0.f}, {0.f, 0.f}};
        int qg[2][2];
#pragma unroll
        for (int mi = 0; mi < 2; mi++) {
            qg[mi][0] = qt * 128 + m0 + mi * 16 + g;
            qg[mi][1] = qg[mi][0] + 8;
        }

        const int klast  = 2 * qt + 1;
        const int kend_w = 2 * qt + (w >= 2 ? 1 : 0);

        int buf = 0;
        for (int kb = 0; kb <= klast; kb++) {
            if (kb < klast) { loadKV(kb + 1, buf ^ 1); cp_commit(); cp_wait<1>(); }
            else            { cp_wait<0>(); }
            __syncthreads();

            if (kb <= kend_w) {
                const unsigned kstage = base + FQ_B + (unsigned)buf * FKV_B;
                const unsigned* Ks = (const unsigned*)(smf + FQ_B + buf * FKV_B);
                const unsigned vB = kstage + 9216u + vlane;

                float s[2][8][4];
#pragma unroll
                for (int mi = 0; mi < 2; mi++)
#pragma unroll
                    for (int nt = 0; nt < 8; nt++)
                        s[mi][nt][0] = s[mi][nt][1] = s[mi][nt][2] = s[mi][nt][3] = 0.f;
#pragma unroll
                for (int nt = 0; nt < 8; nt++) {
                    int n = nt * 8 + g;
#pragma unroll
                    for (int kt = 0; kt < 4; kt++) {
                        unsigned bb[2];
                        bb[0] = Ks[n * 36 + tig + 8 * kt];
                        bb[1] = Ks[n * 36 + tig + 4 + 8 * kt];
                        mma_f16(s[0][nt], qf[0][kt], bb);
                        mma_f16(s[1][nt], qf[1][kt], bb);
                    }
                }

                if (kb == kend_w) {
#pragma unroll
                    for (int mi = 0; mi < 2; mi++)
#pragma unroll
                        for (int nt = 0; nt < 8; nt++) {
                            int kg = kb * 64 + nt * 8 + 2 * tig;
                            if (kg > qg[mi][0])     s[mi][nt][0] = -1e30f;
                            if (kg + 1 > qg[mi][0]) s[mi][nt][1] = -1e30f;
                            if (kg > qg[mi][1])     s[mi][nt][2] = -1e30f;
                            if (kg + 1 > qg[mi][1]) s[mi][nt][3] = -1e30f;
                        }
                }

                unsigned p[2][8][2];
#pragma unroll
                for (int mi = 0; mi < 2; mi++) {
                    float vm0 = -1e30f, vm1 = -1e30f;
#pragma unroll
                    for (int nt = 0; nt < 8; nt++) {
                        vm0 = fmaxf(vm0, fmaxf(s[mi][nt][0], s[mi][nt][1]));
                        vm1 = fmaxf(vm1, fmaxf(s[mi][nt][2], s[mi][nt][3]));
                    }
                    vm0 = fmaxf(vm0, __shfl_xor_sync(0xffffffffu, vm0, 1));
                    vm0 = fmaxf(vm0, __shfl_xor_sync(0xffffffffu, vm0, 2));
                    vm1 = fmaxf(vm1, __shfl_xor_sync(0xffffffffu, vm1, 1));
                    vm1 = fmaxf(vm1, __shfl_xor_sync(0xffffffffu, vm1, 2));

                    float mn0 = fmaxf(mr[mi][0], vm0), mn1 = fmaxf(mr[mi][1], vm1);
                    float corr0 = ex2f(mr[mi][0] - mn0), corr1 = ex2f(mr[mi][1] - mn1);
                    mr[mi][0] = mn0; mr[mi][1] = mn1;

                    float sum0 = 0.f, sum1 = 0.f;
#pragma unroll
                    for (int nt = 0; nt < 8; nt++) {
                        unsigned h01 = packh2(s[mi][nt][0] - mn0, s[mi][nt][1] - mn0);
                        unsigned h23 = packh2(s[mi][nt][2] - mn1, s[mi][nt][3] - mn1);
                        unsigned p01 = h2ex2(h01);
                        unsigned p23 = h2ex2(h23);
                        p[mi][nt][0] = p01;
                        p[mi][nt][1] = p23;
                        float2 f01 = h2f2(p01);
                        float2 f23 = h2f2(p23);
                        sum0 += f01.x + f01.y;
                        sum1 += f23.x + f23.y;
                    }
                    sum0 += __shfl_xor_sync(0xffffffffu, sum0, 1);
                    sum0 += __shfl_xor_sync(0xffffffffu, sum0, 2);
                    sum1 += __shfl_xor_sync(0xffffffffu, sum1, 1);
                    sum1 += __shfl_xor_sync(0xffffffffu, sum1, 2);
                    l[mi][0] = l[mi][0] * corr0 + sum0;
                    l[mi][1] = l[mi][1] * corr1 + sum1;

#pragma unroll
                    for (int nt = 0; nt < 8; nt++) {
                        o[mi][nt][0] *= corr0; o[mi][nt][1] *= corr0;
                        o[mi][nt][2] *= corr1; o[mi][nt][3] *= corr1;
                    }
                }

#pragma unroll
                for (int kt = 0; kt < 4; kt++) {
                    unsigned pa0[4], pa1[4];
                    pa0[0] = p[0][2 * kt][0];     pa0[1] = p[0][2 * kt][1];
                    pa0[2] = p[0][2 * kt + 1][0]; pa0[3] = p[0][2 * kt + 1][1];
                    pa1[0] = p[1][2 * kt][0];     pa1[1] = p[1][2 * kt][1];
                    pa1[2] = p[1][2 * kt + 1][0]; pa1[3] = p[1][2 * kt + 1][1];
                    unsigned vrowbase = vB + (unsigned)(kt * 2304);
#pragma unroll
                    for (int ntp = 0; ntp < 4; ntp++) {
                        unsigned vr[4];
                        ldsm4t(vr, vrowbase + ntp * 32);
                        unsigned b0[2] = {vr[0], vr[1]};
                        unsigned b1[2] = {vr[2], vr[3]};
                        mma_f16(o[0][2 * ntp],     pa0, b0);
                        mma_f16(o[0][2 * ntp + 1], pa0, b1);
                        mma_f16(o[1][2 * ntp],     pa1, b0);
                        mma_f16(o[1][2 * ntp + 1], pa1, b1);
                    }
                }
            }
            __syncthreads();
            buf ^= 1;
        }

#pragma unroll
        for (int mi = 0; mi < 2; mi++) {
            float inv0 = 1.f / l[mi][0], inv1 = 1.f / l[mi][1];
            __half* op0 = out + (size_t)(b * TT + qg[mi][0]) * CC + h * DH;
            __half* op1 = out + (size_t)(b * TT + qg[mi][1]) * CC + h * DH;
#pragma unroll
            for (int nt = 0; nt < 8; nt++) {
                *(unsigned*)(op0 + nt * 8 + 2 * tig) =
                    packh2(o[mi][nt][0] * inv0, o[mi][nt][1] * inv0);
                *(unsigned*)(op1 + nt * 8 + 2 * tig) =
                    packh2(o[mi][nt][2] * inv1, o[mi][nt][3] * inv1);
            }
        }
    }
}

// ---------------------------------------------------------------------------
// kernel_launch
// ---------------------------------------------------------------------------
extern "C" void kernel_launch(void* const* d_in, const int* in_sizes, int n_in,
                              void* d_out, int out_size)
{
    const float* x    = (const float*)d_in[0];
    // d_in[1] = mask (static causal; unused)
    const float* Wqkv = (const float*)d_in[2];
    const float* bqkv = (const float*)d_in[3];
    const float* Wout = (const float*)d_in[4];
    const float* bout = (const float*)d_in[5];
    float* out = (float*)d_out;

    __half* qkvh;  cudaGetSymbolAddress((void**)&qkvh,  g_qkvh);
    __half* atth;  cudaGetSymbolAddress((void**)&atth,  g_atth);
    __half* xh;    cudaGetSymbolAddress((void**)&xh,    g_xh);
    __half* wqkvh; cudaGetSymbolAddress((void**)&wqkvh, g_wqkvh);
    __half* wouth; cudaGetSymbolAddress((void**)&wouth, g_wouth);

    static bool configured = false;
    if (!configured) {
        cudaFuncSetAttribute(gemm_f16<true>,
                             cudaFuncAttributeMaxDynamicSharedMemorySize, GEMM_SMEM);
        cudaFuncSetAttribute(gemm_f16_n64_sk,
                             cudaFuncAttributeMaxDynamicSharedMemorySize, G64_SMEM);
        cudaFuncSetAttribute(flash_f16,
                             cudaFuncAttributeMaxDynamicSharedMemorySize, FLASH_SMEM);
        configured = true;
    }

    const float QSCALE = 0.125f * 1.44269504088896341f;   // 1/sqrt(64) * log2(e)

    // 0) fused pre-pass: x conversion + weight transposes + zero out
    prepass_kernel<<<NB_PRE, 256>>>(x, Wqkv, Wout, xh, wqkvh, wouth, out);

    // 1) QKV projection (q-columns pre-scaled by QSCALE; fp16 output)
    {
        dim3 grid(C3 / 128, MM / 128);
        gemm_f16<true><<<grid, 128, GEMM_SMEM>>>(xh, wqkvh, bqkv, qkvh,
                                                 MM, C3, CC, QSCALE);
    }
    // 2) Causal multi-head attention (fp16 output), paired q-tiles
    {
        dim3 grid(TT / 256, NH, BB);     // 8 x 12 x 2 = 192 balanced blocks
        flash_f16<<<grid, 128, FLASH_SMEM>>>(qkvh, atth);
    }
    // 3) Output projection (fp32 atomic output), 128x64 tiles, split-K=2
    {
        dim3 grid(CC / 64, MM / 128, 2);  // 768 blocks
        gemm_f16_n64_sk<<<grid, 128, G64_SMEM>>>(atth, wouth, bout, out,
                                                 MM, CC, CC);
    }
}

// round 16
// speedup vs baseline: 1.0397x; 1.0397x over previous
#include <cuda_runtime.h>
#include <cuda_fp16.h>
#include <cstdint>

// Problem constants
#define BB      2
#define TT      2048
#define NH      12
#define DH      64
#define CC      768      // d_model
#define C3      2304     // 3*d_model
#define MM      (BB*TT)  // 4096 rows

// Scratch (device globals — no runtime allocation allowed)
__device__ __half g_qkvh[(size_t)MM * C3];    // [4096, 2304] fp16
__device__ __half g_atth[(size_t)MM * CC];    // [4096, 768]  fp16
__device__ __half g_xh[(size_t)MM * CC];      // x fp16
__device__ __half g_wqkvh[(size_t)C3 * CC];   // Wqkv^T fp16 [2304][768]
__device__ __half g_wouth[(size_t)CC * CC];   // Wout^T fp16 [768][768]

// ---------------------------------------------------------------------------
// helpers
// ---------------------------------------------------------------------------
__device__ __forceinline__ float ex2f(float x) {
    float r; asm("ex2.approx.f32 %0, %1;" : "=f"(r) : "f"(x)); return r;
}
__device__ __forceinline__ unsigned packh2(float lo, float hi) {
    __half2 h = __floats2half2_rn(lo, hi);
    return *reinterpret_cast<unsigned*>(&h);
}
__device__ __forceinline__ unsigned h2ex2(unsigned h) {
    unsigned r; asm("ex2.approx.f16x2 %0, %1;" : "=r"(r) : "r"(h)); return r;
}
__device__ __forceinline__ float2 h2f2(unsigned h) {
    __half2 v = *reinterpret_cast<__half2*>(&h);
    return __half22float2(v);
}
__device__ __forceinline__ void mma_f16(float c[4], const unsigned a[4], const unsigned b[2]) {
    asm volatile(
        "mma.sync.aligned.m16n8k16.row.col.f32.f16.f16.f32 "
        "{%0,%1,%2,%3},{%4,%5,%6,%7},{%8,%9},{%0,%1,%2,%3};"
        : "+f"(c[0]), "+f"(c[1]), "+f"(c[2]), "+f"(c[3])
        : "r"(a[0]), "r"(a[1]), "r"(a[2]), "r"(a[3]), "r"(b[0]), "r"(b[1]));
}
__device__ __forceinline__ void cp16s(unsigned dst_saddr, const void* src) {
    asm volatile("cp.async.cg.shared.global [%0], [%1], 16;" :: "r"(dst_saddr), "l"(src));
}
__device__ __forceinline__ void cp_commit() {
    asm volatile("cp.async.commit_group;");
}
template<int N> __device__ __forceinline__ void cp_wait() {
    asm volatile("cp.async.wait_group %0;" :: "n"(N));
}
__device__ __forceinline__ unsigned saddr(const void* p) {
    return (unsigned)__cvta_generic_to_shared(p);
}
// ldmatrix x4 (b16), transposed — V fragments
__device__ __forceinline__ void ldsm4t(unsigned r[4], unsigned addr) {
    asm volatile("ldmatrix.sync.aligned.m8n8.x4.trans.shared.b16 {%0,%1,%2,%3}, [%4];"
                 : "=r"(r[0]), "=r"(r[1]), "=r"(r[2]), "=r"(r[3]) : "r"(addr));
}

// ---------------------------------------------------------------------------
// Fused pre-pass (R12 version): x f32->f16 plus both weight transposes.
// ---------------------------------------------------------------------------
#define NBX   ((MM * CC / 4) / 256)          // 3072
#define NBWQ  ((C3 / 32) * (CC / 32))        // 1728
#define NBWO  ((CC / 32) * (CC / 32))        // 576
#define NB_PRE (NBX + NBWQ + NBWO)

__global__ __launch_bounds__(256)
void prepass_kernel(const float* __restrict__ x,
                    const float* __restrict__ Wqkv,
                    const float* __restrict__ Wout,
                    __half* __restrict__ xh,
                    __half* __restrict__ wqkvh,
                    __half* __restrict__ wouth)
{
    __shared__ float t[32][33];
    const int bid = blockIdx.x;
    const int tid = threadIdx.x;

    if (bid < NBX) {
        int i = bid * 256 + tid;
        float4 v = ((const float4*)x)[i];
        ((__half2*)xh)[2 * i]     = __floats2half2_rn(v.x, v.y);
        ((__half2*)xh)[2 * i + 1] = __floats2half2_rn(v.z, v.w);
        return;
    }
    const float* in; __half* outp; int K, N, bx, by;
    if (bid < NBX + NBWQ) {
        int tI = bid - NBX;
        bx = tI % (C3 / 32); by = tI / (C3 / 32);
        in = Wqkv; outp = wqkvh; K = CC; N = C3;
    } else {
        int tI = bid - NBX - NBWQ;
        bx = tI % (CC / 32); by = tI / (CC / 32);
        in = Wout; outp = wouth; K = CC; N = CC;
    }
    int n0 = bx * 32, k0 = by * 32;
    int tx = tid & 31, ty = tid >> 5;    // 32 x 8
#pragma unroll
    for (int j = 0; j < 4; j++)
        t[ty + j * 8][tx] = in[(size_t)(k0 + ty + j * 8) * N + n0 + tx];
    __syncthreads();
#pragma unroll
    for (int j = 0; j < 4; j++)
        outp[(size_t)(n0 + ty + j * 8) * K + k0 + tx] = __float2half_rn(t[tx][ty + j * 8]);
}

// ---------------------------------------------------------------------------
// FP16 tensor-core GEMM with bias (128x128 tile; measured best for QKV):
// 4 warps (128 thr), warp tile 64x64, BK=64, 2-stage cp.async.
// ---------------------------------------------------------------------------
#define GSTAGE_B 36864
#define GEMM_SMEM (2 * GSTAGE_B)

template<bool HALF_OUT>
__global__ __launch_bounds__(128, 2)
void gemm_f16(const __half* __restrict__ A, const __half* __restrict__ Bt,
              const float* __restrict__ bias, void* __restrict__ Cv,
              int M, int N, int K, float qmul)
{
    extern __shared__ char smg[];
    const unsigned base = saddr(smg);

    const int tid  = threadIdx.x;
    const int lane = tid & 31;
    const int w    = tid >> 5;
    const int wm   = (w >> 1) * 64;
    const int wn   = (w & 1) * 64;
    const int g    = lane >> 2;
    const int tig  = lane & 3;
    const int rowBase = blockIdx.y * 128;
    const int colBase = blockIdx.x * 128;

    float acc[4][8][4];
#pragma unroll
    for (int mt = 0; mt < 4; mt++)
#pragma unroll
        for (int nt = 0; nt < 8; nt++)
#pragma unroll
            for (int j = 0; j < 4; j++) acc[mt][nt][j] = 0.f;

    auto loadTile = [&](int k0, int s) {
        unsigned ab = base + (unsigned)s * GSTAGE_B;
        unsigned bb = ab + 18432u;
#pragma unroll
        for (int i = 0; i < 8; i++) {
            int idx = tid + i * 128;
            int r = idx >> 3, c = idx & 7;
            cp16s(ab + r * 144 + c * 16, A  + (size_t)(rowBase + r) * K + k0 + c * 8);
        }
#pragma unroll
        for (int i = 0; i < 8; i++) {
            int idx = tid + i * 128;
            int r = idx >> 3, c = idx & 7;
            cp16s(bb + r * 144 + c * 16, Bt + (size_t)(colBase + r) * K + k0 + c * 8);
        }
    };

    loadTile(0, 0);
    cp_commit();

    int buf = 0;
    for (int k0 = 0; k0 < K; k0 += 64) {
        if (k0 + 64 < K) { loadTile(k0 + 64, buf ^ 1); cp_commit(); cp_wait<1>(); }
        else             { cp_wait<0>(); }
        __syncthreads();

        const unsigned* As = (const unsigned*)(smg + buf * GSTAGE_B);
        const unsigned* Bs = As + 18432 / 4;

#pragma unroll
        for (int ks = 0; ks < 4; ks++) {
            unsigned af[4][4], bf[8][2];
#pragma unroll
            for (int mt = 0; mt < 4; mt++) {
                int m = wm + mt * 16 + g;
                af[mt][0] = As[m * 36 + tig + 8 * ks];
                af[mt][1] = As[(m + 8) * 36 + tig + 8 * ks];
                af[mt][2] = As[m * 36 + tig + 4 + 8 * ks];
                af[mt][3] = As[(m + 8) * 36 + tig + 4 + 8 * ks];
            }
#pragma unroll
            for (int nt = 0; nt < 8; nt++) {
                int n = wn + nt * 8 + g;
                bf[nt][0] = Bs[n * 36 + tig + 8 * ks];
                bf[nt][1] = Bs[n * 36 + tig + 4 + 8 * ks];
            }
#pragma unroll
            for (int mt = 0; mt < 4; mt++)
#pragma unroll
                for (int nt = 0; nt < 8; nt++)
                    mma_f16(acc[mt][nt], af[mt], bf[nt]);
        }
        __syncthreads();
        buf ^= 1;
    }

#pragma unroll
    for (int mt = 0; mt < 4; mt++) {
        int r0 = rowBase + wm + mt * 16 + g;
#pragma unroll
        for (int nt = 0; nt < 8; nt++) {
            int c = colBase + wn + nt * 8 + 2 * tig;
            float2 b2 = *(const float2*)(bias + c);
            float sc = (c < CC) ? qmul : 1.f;
            float v00 = (acc[mt][nt][0] + b2.x) * sc, v01 = (acc[mt][nt][1] + b2.y) * sc;
            float v10 = (acc[mt][nt][2] + b2.x) * sc, v11 = (acc[mt][nt][3] + b2.y) * sc;
            if (HALF_OUT) {
                __half* C = (__half*)Cv;
                *(unsigned*)(C + (size_t)r0 * N + c)       = packh2(v00, v01);
                *(unsigned*)(C + (size_t)(r0 + 8) * N + c) = packh2(v10, v11);
            } else {
                float* C = (float*)Cv;
                *(float2*)(C + (size_t)r0 * N + c)       = make_float2(v00, v01);
                *(float2*)(C + (size_t)(r0 + 8) * N + c) = make_float2(v10, v11);
            }
        }
    }
}

// ---------------------------------------------------------------------------
// FP16 GEMM, 128x64 block tile, 4 warps (R12 config — measured best 25.5us).
// smem: 2 stages x (A[128][72] + B[64][72]) halves = 55296 B; 3 blocks/SM.
// ---------------------------------------------------------------------------
#define G64_STAGE_B 27648
#define G64_SMEM (2 * G64_STAGE_B)

__global__ __launch_bounds__(128, 3)
void gemm_f16_n64(const __half* __restrict__ A, const __half* __restrict__ Bt,
                  const float* __restrict__ bias, float* __restrict__ C,
                  int M, int N, int K)
{
    extern __shared__ char smg[];
    const unsigned base = saddr(smg);

    const int tid  = threadIdx.x;
    const int lane = tid & 31;
    const int w    = tid >> 5;
    const int wm   = w * 32;
    const int g    = lane >> 2;
    const int tig  = lane & 3;
    const int rowBase = blockIdx.y * 128;
    const int colBase = blockIdx.x * 64;

    float acc[2][8][4];
#pragma unroll
    for (int mt = 0; mt < 2; mt++)
#pragma unroll
        for (int nt = 0; nt < 8; nt++)
#pragma unroll
            for (int j = 0; j < 4; j++) acc[mt][nt][j] = 0.f;

    auto loadTile = [&](int k0, int s) {
        unsigned ab = base + (unsigned)s * G64_STAGE_B;
        unsigned bb = ab + 18432u;
#pragma unroll
        for (int i = 0; i < 8; i++) {
            int idx = tid + i * 128;
            int r = idx >> 3, c = idx & 7;
            cp16s(ab + r * 144 + c * 16, A  + (size_t)(rowBase + r) * K + k0 + c * 8);
        }
#pragma unroll
        for (int i = 0; i < 4; i++) {
            int idx = tid + i * 128;
            int r = idx >> 3, c = idx & 7;
            cp16s(bb + r * 144 + c * 16, Bt + (size_t)(colBase + r) * K + k0 + c * 8);
        }
    };

    loadTile(0, 0);
    cp_commit();

    int buf = 0;
    for (int k0 = 0; k0 < K; k0 += 64) {
        if (k0 + 64 < K) { loadTile(k0 + 64, buf ^ 1); cp_commit(); cp_wait<1>(); }
        else             { cp_wait<0>(); }
        __syncthreads();

        const unsigned* As = (const unsigned*)(smg + buf * G64_STAGE_B);
        const unsigned* Bs = As + 18432 / 4;

#pragma unroll
        for (int ks = 0; ks < 4; ks++) {
            unsigned af[2][4], bf[8][2];
#pragma unroll
            for (int mt = 0; mt < 2; mt++) {
                int m = wm + mt * 16 + g;
                af[mt][0] = As[m * 36 + tig + 8 * ks];
                af[mt][1] = As[(m + 8) * 36 + tig + 8 * ks];
                af[mt][2] = As[m * 36 + tig + 4 + 8 * ks];
                af[mt][3] = As[(m + 8) * 36 + tig + 4 + 8 * ks];
            }
#pragma unroll
            for (int nt = 0; nt < 8; nt++) {
                int n = nt * 8 + g;
                bf[nt][0] = Bs[n * 36 + tig + 8 * ks];
                bf[nt][1] = Bs[n * 36 + tig + 4 + 8 * ks];
            }
#pragma unroll
            for (int mt = 0; mt < 2; mt++)
#pragma unroll
                for (int nt = 0; nt < 8; nt++)
                    mma_f16(acc[mt][nt], af[mt], bf[nt]);
        }
        __syncthreads();
        buf ^= 1;
    }

#pragma unroll
    for (int mt = 0; mt < 2; mt++) {
        int r0 = rowBase + wm + mt * 16 + g;
#pragma unroll
        for (int nt = 0; nt < 8; nt++) {
            int c = colBase + nt * 8 + 2 * tig;
            float2 b2 = *(const float2*)(bias + c);
            *(float2*)(C + (size_t)r0 * N + c) =
                make_float2(acc[mt][nt][0] + b2.x, acc[mt][nt][1] + b2.y);
            *(float2*)(C + (size_t)(r0 + 8) * N + c) =
                make_float2(acc[mt][nt][2] + b2.x, acc[mt][nt][3] + b2.y);
        }
    }
}

// ---------------------------------------------------------------------------
// Causal flash attention (R12 body): paired q-tiles, 4 warps x M=32,
// f16x2 softmax, 2-stage cp.async K/V, V via ldmatrix.trans.
// R16 change: Q tile loaded via cp.async in the SAME group as K/V tile 0 —
// removes the serial LDG->STS Q stall at each q-tile start.
// smem: Q[128][72] | 2 x (K[64][72] + V[64][72]) = 55296 B -> 2 blocks/SM.
// ---------------------------------------------------------------------------
#define FQ_B     18432
#define FKV_B    18432
#define FLASH_SMEM (FQ_B + 2 * FKV_B)

__global__ __launch_bounds__(128, 2)
void flash_f16(const __half* __restrict__ qkv, __half* __restrict__ out)
{
    extern __shared__ char smf[];
    const unsigned base = saddr(smf);

    const int b    = blockIdx.z;
    const int h    = blockIdx.y;
    const int tid  = threadIdx.x;
    const int lane = tid & 31;
    const int w    = tid >> 5;
    const int g    = lane >> 2;
    const int tig  = lane & 3;
    const int m0   = w * 32;
    const int nq   = gridDim.x * 2;
    const unsigned vlane = (unsigned)((lane & 15) * 144 + (lane >> 4) * 16);

    auto loadKV = [&](int kb, int s) {
        unsigned kbase = base + FQ_B + (unsigned)s * FKV_B;
        unsigned vbase = kbase + 9216u;
        const __half* kp = qkv + (size_t)(b * TT + kb * 64) * C3 + CC + h * DH;
#pragma unroll
        for (int i = 0; i < 4; i++) {
            int idx = tid + i * 128;
            int r = idx >> 3, c = idx & 7;
            const __half* rp = kp + (size_t)r * C3 + c * 8;
            cp16s(kbase + r * 144 + c * 16, rp);
            cp16s(vbase + r * 144 + c * 16, rp + CC);
        }
    };
    auto loadQ = [&](int qt) {
        const __half* qp = qkv + (size_t)(b * TT + qt * 128) * C3 + h * DH;
#pragma unroll
        for (int i = 0; i < 8; i++) {
            int idx = tid + i * 128;
            int r = idx >> 3, c = idx & 7;
            cp16s(base + r * 144 + c * 16, qp + (size_t)r * C3 + c * 8);
        }
    };

    const int qts[2] = { nq - 1 - (int)blockIdx.x, (int)blockIdx.x };

    for (int qi = 0; qi < 2; qi++) {
        const int qt = qts[qi];

        // Q + K/V tile 0 in one async group; single wait covers both.
        loadKV(0, 0);
        loadQ(qt);
        cp_commit();
        cp_wait<0>();
        __syncthreads();

        // ---- persistent Q fragments: 2 m-tiles x 4 k-steps ----
        unsigned qf[2][4][4];
        {
            const unsigned* Qs = (const unsigned*)smf;
#pragma unroll
            for (int mi = 0; mi < 2; mi++) {
                int m = m0 + mi * 16 + g;
#pragma unroll
                for (int kt = 0; kt < 4; kt++) {
                    qf[mi][kt][0] = Qs[m * 36 + tig + 8 * kt];
                    qf[mi][kt][1] = Qs[(m + 8) * 36 + tig + 8 * kt];
                    qf[mi][kt][2] = Qs[m * 36 + tig + 4 + 8 * kt];
                    qf[mi][kt][3] = Qs[(m + 8) * 36 + tig + 4 + 8 * kt];
                }
            }
        }

        float o[2][8][4];
#pragma unroll
        for (int mi = 0; mi < 2; mi++)
#pragma unroll
            for (int nt = 0; nt < 8; nt++)
#pragma unroll
                for (int j = 0; j < 4; j++) o[mi][nt][j] = 0.f;

        float mr[2][2] = {{-1e30f, -1e30f}, {-1e30f, -1e30f}};
        float l[2][2]  = {{0.f, 0.f}, {0.f, 0.f}};
        int qg[2][2];
#pragma unroll
        for (int mi = 0; mi < 2; mi++) {
            qg[mi][0] = qt * 128 + m0 + mi * 16 + g;
            qg[mi][1] = qg[mi][0] + 8;
        }

        const int klast  = 2 * qt + 1;
        const int kend_w = 2 * qt + (w >= 2 ? 1 : 0);

        int buf = 0;
        for (int kb = 0; kb <= klast; kb++) {
            if (kb < klast) { loadKV(kb + 1, buf ^ 1); cp_commit(); cp_wait<1>(); }
            else            { cp_wait<0>(); }
            __syncthreads();

            if (kb <= kend_w) {
                const unsigned kstage = base + FQ_B + (unsigned)buf * FKV_B;
                const unsigned* Ks = (const unsigned*)(smf + FQ_B + buf * FKV_B);
                const unsigned vB = kstage + 9216u + vlane;

                float s[2][8][4];
#pragma unroll
                for (int mi = 0; mi < 2; mi++)
#pragma unroll
                    for (int nt = 0; nt < 8; nt++)
                        s[mi][nt][0] = s[mi][nt][1] = s[mi][nt][2] = s[mi][nt][3] = 0.f;
#pragma unroll
                for (int nt = 0; nt < 8; nt++) {
                    int n = nt * 8 + g;
#pragma unroll
                    for (int kt = 0; kt < 4; kt++) {
                        unsigned bb[2];
                        bb[0] = Ks[n * 36 + tig + 8 * kt];
                        bb[1] = Ks[n * 36 + tig + 4 + 8 * kt];
                        mma_f16(s[0][nt], qf[0][kt], bb);
                        mma_f16(s[1][nt], qf[1][kt], bb);
                    }
                }

                if (kb == kend_w) {
#pragma unroll
                    for (int mi = 0; mi < 2; mi++)
#pragma unroll
                        for (int nt = 0; nt < 8; nt++) {
                            int kg = kb * 64 + nt * 8 + 2 * tig;
                            if (kg > qg[mi][0])     s[mi][nt][0] = -1e30f;
                            if (kg + 1 > qg[mi][0]) s[mi][nt][1] = -1e30f;
                            if (kg > qg[mi][1])     s[mi][nt][2] = -1e30f;
                            if (kg + 1 > qg[mi][1]) s[mi][nt][3] = -1e30f;
                        }
                }

                unsigned p[2][8][2];
#pragma unroll
                for (int mi = 0; mi < 2; mi++) {
                    float vm0 = -1e30f, vm1 = -1e30f;
#pragma unroll
                    for (int nt = 0; nt < 8; nt++) {
                        vm0 = fmaxf(vm0, fmaxf(s[mi][nt][0], s[mi][nt][1]));
                        vm1 = fmaxf(vm1, fmaxf(s[mi][nt][2], s[mi][nt][3]));
                    }
                    vm0 = fmaxf(vm0, __shfl_xor_sync(0xffffffffu, vm0, 1));
                    vm0 = fmaxf(vm0, __shfl_xor_sync(0xffffffffu, vm0, 2));
                    vm1 = fmaxf(vm1, __shfl_xor_sync(0xffffffffu, vm1, 1));
                    vm1 = fmaxf(vm1, __shfl_xor_sync(0xffffffffu, vm1, 2));

                    float mn0 = fmaxf(mr[mi][0], vm0), mn1 = fmaxf(mr[mi][1], vm1);
                    float corr0 = ex2f(mr[mi][0] - mn0), corr1 = ex2f(mr[mi][1] - mn1);
                    mr[mi][0] = mn0; mr[mi][1] = mn1;

                    float sum0 = 0.f, sum1 = 0.f;
#pragma unroll
                    for (int nt = 0; nt < 8; nt++) {
                        unsigned h01 = packh2(s[mi][nt][0] - mn0, s[mi][nt][1] - mn0);
                        unsigned h23 = packh2(s[mi][nt][2] - mn1, s[mi][nt][3] - mn1);
                        unsigned p01 = h2ex2(h01);
                        unsigned p23 = h2ex2(h23);
                        p[mi][nt][0] = p01;
                        p[mi][nt][1] = p23;
                        float2 f01 = h2f2(p01);
                        float2 f23 = h2f2(p23);
                        sum0 += f01.x + f01.y;
                        sum1 += f23.x + f23.y;
                    }
                    sum0 += __shfl_xor_sync(0xffffffffu, sum0, 1);
                    sum0 += __shfl_xor_sync(0xffffffffu, sum0, 2);
                    sum1 += __shfl_xor_sync(0xffffffffu, sum1, 1);
                    sum1 += __shfl_xor_sync(0xffffffffu, sum1, 2);
                    l[mi][0] = l[mi][0] * corr0 + sum0;
                    l[mi][1] = l[mi][1] * corr1 + sum1;

#pragma unroll
                    for (int nt = 0; nt < 8; nt++) {
                        o[mi][nt][0] *= corr0; o[mi][nt][1] *= corr0;
                        o[mi][nt][2] *= corr1; o[mi][nt][3] *= corr1;
                    }
                }

#pragma unroll
                for (int kt = 0; kt < 4; kt++) {
                    unsigned pa0[4], pa1[4];
                    pa0[0] = p[0][2 * kt][0];     pa0[1] = p[0][2 * kt][1];
                    pa0[2] = p[0][2 * kt + 1][0]; pa0[3] = p[0][2 * kt + 1][1];
                    pa1[0] = p[1][2 * kt][0];     pa1[1] = p[1][2 * kt][1];
                    pa1[2] = p[1][2 * kt + 1][0]; pa1[3] = p[1][2 * kt + 1][1];
                    unsigned vrowbase = vB + (unsigned)(kt * 2304);
#pragma unroll
                    for (int ntp = 0; ntp < 4; ntp++) {
                        unsigned vr[4];
                        ldsm4t(vr, vrowbase + ntp * 32);
                        unsigned b0[2] = {vr[0], vr[1]};
                        unsigned b1[2] = {vr[2], vr[3]};
                        mma_f16(o[0][2 * ntp],     pa0, b0);
                        mma_f16(o[0][2 * ntp + 1], pa0, b1);
                        mma_f16(o[1][2 * ntp],     pa1, b0);
                        mma_f16(o[1][2 * ntp + 1], pa1, b1);
                    }
                }
            }
            __syncthreads();
            buf ^= 1;
        }

#pragma unroll
        for (int mi = 0; mi < 2; mi++) {
            float inv0 = 1.f / l[mi][0], inv1 = 1.f / l[mi][1];
            __half* op0 = out + (size_t)(b * TT + qg[mi][0]) * CC + h * DH;
            __half* op1 = out + (size_t)(b * TT + qg[mi][1]) * CC + h * DH;
#pragma unroll
            for (int nt = 0; nt < 8; nt++) {
                *(unsigned*)(op0 + nt * 8 + 2 * tig) =
                    packh2(o[mi][nt][0] * inv0, o[mi][nt][1] * inv0);
                *(unsigned*)(op1 + nt * 8 + 2 * tig) =
                    packh2(o[mi][nt][2] * inv1, o[mi][nt][3] * inv1);
            }
        }
    }
}

// ---------------------------------------------------------------------------
// kernel_launch
// ---------------------------------------------------------------------------
extern "C" void kernel_launch(void* const* d_in, const int* in_sizes, int n_in,
                              void* d_out, int out_size)
{
    const float* x    = (const float*)d_in[0];
    // d_in[1] = mask (static causal; unused)
    const float* Wqkv = (const float*)d_in[2];
    const float* bqkv = (const float*)d_in[3];
    const float* Wout = (const float*)d_in[4];
    const float* bout = (const float*)d_in[5];
    float* out = (float*)d_out;

    __half* qkvh;  cudaGetSymbolAddress((void**)&qkvh,  g_qkvh);
    __half* atth;  cudaGetSymbolAddress((void**)&atth,  g_atth);
    __half* xh;    cudaGetSymbolAddress((void**)&xh,    g_xh);
    __half* wqkvh; cudaGetSymbolAddress((void**)&wqkvh, g_wqkvh);
    __half* wouth; cudaGetSymbolAddress((void**)&wouth, g_wouth);

    static bool configured = false;
    if (!configured) {
        cudaFuncSetAttribute(gemm_f16<true>,
                             cudaFuncAttributeMaxDynamicSharedMemorySize, GEMM_SMEM);
        cudaFuncSetAttribute(gemm_f16_n64,
                             cudaFuncAttributeMaxDynamicSharedMemorySize, G64_SMEM);
        cudaFuncSetAttribute(flash_f16,
                             cudaFuncAttributeMaxDynamicSharedMemorySize, FLASH_SMEM);
        configured = true;
    }

    const float QSCALE = 0.125f * 1.44269504088896341f;   // 1/sqrt(64) * log2(e)

    // 0) fused pre-pass: x conversion + both weight transposes, one launch
    prepass_kernel<<<NB_PRE, 256>>>(x, Wqkv, Wout, xh, wqkvh, wouth);

    // 1) QKV projection (q-columns pre-scaled by QSCALE; fp16 output)
    {
        dim3 grid(C3 / 128, MM / 128);
        gemm_f16<true><<<grid, 128, GEMM_SMEM>>>(xh, wqkvh, bqkv, qkvh,
                                                 MM, C3, CC, QSCALE);
    }
    // 2) Causal multi-head attention (fp16 output), paired q-tiles
    {
        dim3 grid(TT / 256, NH, BB);     // 8 x 12 x 2 = 192 balanced blocks
        flash_f16<<<grid, 128, FLASH_SMEM>>>(qkvh, atth);
    }
    // 3) Output projection (fp32 output), 128x64 tiles -> 384 blocks
    {
        dim3 grid(CC / 64, MM / 128);
        gemm_f16_n64<<<grid, 128, G64_SMEM>>>(atth, wouth, bout, out,
                                              MM, CC, CC);
    }
}